// round 14
// baseline (speedup 1.0000x reference)
#include <cuda_runtime.h>
#include <cuda_fp16.h>
#include <math.h>
#include <stdint.h>

#define BATCH  2
#define CH     512
#define NPIX   4096
#define GROUPS 32
#define CPG    16
#define EPS    1e-6f
#define NSTG   4         // pipeline stages
#define BK     32
#define PIT    40        // smem row pitch in halfs
#define STG_HALFS (128*PIT)          // per operand per stage
#define STG_BYTES (STG_HALFS*2*2)    // A+B per stage = 20480 B
#define SMEM_BYTES (1024 + NSTG*STG_BYTES)

// ---------------- scratch (device globals; no allocation) ----------------
__device__ __align__(256) __half g_hnT[(size_t)BATCH*NPIX*CH];  // [pix][ch]
__device__ __align__(256) __half g_qT [(size_t)BATCH*NPIX*CH];  // [pix][ch]
__device__ __align__(256) __half g_kT [(size_t)BATCH*NPIX*CH];  // [pix][ch]
__device__ __align__(256) __half g_v  [(size_t)BATCH*CH*NPIX];  // [ch][pix]
__device__ __align__(256) __half g_e  [(size_t)BATCH*NPIX*NPIX];// [i][j]
__device__ __align__(256) __half g_oT [(size_t)BATCH*NPIX*CH];  // [i][ch]
__device__ __align__(256) __half g_wh [(size_t)4*CH*CH];        // wq|wk|wv|wo
__device__ float g_S   [(size_t)BATCH*NPIX];
__device__ float g_Sinv[(size_t)BATCH*NPIX];
__device__ float g_stat[(size_t)BATCH*GROUPS*2];

// ---------------- GroupNorm stats ----------------
__global__ void gn_stats_kernel(const float* __restrict__ x)
{
    const int b = blockIdx.y, g = blockIdx.x;
    const size_t base = ((size_t)b*CH + (size_t)g*CPG) * NPIX;
    const float* xp = x + base;
    const int NE = CPG * NPIX;

    float s = 0.f, ss = 0.f;
    for (int i = threadIdx.x*4; i < NE; i += blockDim.x*4) {
        float4 v = *(const float4*)(xp + i);
        s  += v.x + v.y + v.z + v.w;
        ss += v.x*v.x + v.y*v.y + v.z*v.z + v.w*v.w;
    }
    __shared__ float sh1[256], sh2[256];
    sh1[threadIdx.x] = s; sh2[threadIdx.x] = ss;
    __syncthreads();
    for (int o = 128; o > 0; o >>= 1) {
        if (threadIdx.x < o) {
            sh1[threadIdx.x] += sh1[threadIdx.x + o];
            sh2[threadIdx.x] += sh2[threadIdx.x + o];
        }
        __syncthreads();
    }
    if (threadIdx.x == 0) {
        float mu  = sh1[0] / (float)NE;
        float var = sh2[0] / (float)NE - mu*mu;
        g_stat[(b*GROUPS + g)*2 + 0] = mu;
        g_stat[(b*GROUPS + g)*2 + 1] = rsqrtf(var + EPS);
    }
}

// ---------------- transpose + normalize -> hnT fp16 [pix][ch] ----------------
__global__ void tnorm_kernel(const float* __restrict__ x,
                             const float* __restrict__ gamma,
                             const float* __restrict__ beta)
{
    __shared__ float t[64][65];
    const int p0 = blockIdx.x*64, c0 = blockIdx.y*64, b = blockIdx.z;
    const float* xb = x + (size_t)b*CH*NPIX;
    __half* hb = g_hnT + (size_t)b*NPIX*CH;
    const int tid = threadIdx.x;

    #pragma unroll
    for (int i = 0; i < 4; i++) {
        int idx = tid + i*256;
        int ch = idx >> 4;
        int ps = (idx & 15) * 4;
        int c  = c0 + ch;
        float mu  = g_stat[(b*GROUPS + (c>>4))*2 + 0];
        float inv = g_stat[(b*GROUPS + (c>>4))*2 + 1] * gamma[c];
        float be  = beta[c] - mu*inv;
        float4 v = *(const float4*)(xb + (size_t)c*NPIX + p0 + ps);
        t[ch][ps+0] = v.x*inv + be;
        t[ch][ps+1] = v.y*inv + be;
        t[ch][ps+2] = v.z*inv + be;
        t[ch][ps+3] = v.w*inv + be;
    }
    __syncthreads();
    #pragma unroll
    for (int i = 0; i < 4; i++) {
        int idx = tid + i*256;
        int p  = idx >> 4;
        int cs = (idx & 15) * 4;
        __half2 h01 = __floats2half2_rn(t[cs+0][p], t[cs+1][p]);
        __half2 h23 = __floats2half2_rn(t[cs+2][p], t[cs+3][p]);
        uint2 w;
        w.x = *(uint32_t*)&h01;
        w.y = *(uint32_t*)&h23;
        *(uint2*)(hb + (size_t)(p0+p)*CH + c0 + cs) = w;
    }
}

// ---------------- prep: weight fp32->fp16 + zero rowsums ----------------
__global__ void prep_kernel(const float* __restrict__ wq, const float* __restrict__ wk,
                            const float* __restrict__ wv, const float* __restrict__ wo)
{
    int i = blockIdx.x * blockDim.x + threadIdx.x;
    if (i < BATCH*NPIX) g_S[i] = 0.f;
    const int per = CH*CH;
    if (i >= 4*per) return;
    int m = i / per, off = i - m*per;
    const float* s = (m == 0) ? wq : (m == 1) ? wk : (m == 2) ? wv : wo;
    g_wh[i] = __float2half(s[off]);
}

// ---------------- reciprocal of rowsums ----------------
__global__ void recip_kernel()
{
    int i = blockIdx.x * blockDim.x + threadIdx.x;
    if (i < BATCH*NPIX) g_Sinv[i] = __fdividef(1.f, g_S[i]);
}

// ---------------- low-level helpers ----------------
__device__ __forceinline__ uint32_t smem_u32(const void* p) {
    return (uint32_t)__cvta_generic_to_shared(p);
}
__device__ __forceinline__ void cp16(uint32_t dst, const __half* src) {
    asm volatile("cp.async.cg.shared.global [%0], [%1], 16;" :: "r"(dst), "l"(src));
}
__device__ __forceinline__ void mbar_init(uint32_t a, uint32_t cnt) {
    asm volatile("mbarrier.init.shared.b64 [%0], %1;" :: "r"(a), "r"(cnt) : "memory");
}
__device__ __forceinline__ void mbar_arrive(uint32_t a) {
    asm volatile("mbarrier.arrive.shared.b64 _, [%0];" :: "r"(a) : "memory");
}
__device__ __forceinline__ void mbar_wait(uint32_t a, uint32_t parity) {
    asm volatile(
        "{\n\t.reg .pred P;\n\t"
        "LW_%=:\n\t"
        "mbarrier.try_wait.parity.acquire.cta.shared::cta.b64 P, [%0], %1, 0x989680;\n\t"
        "@P bra LD_%=;\n\t"
        "bra LW_%=;\n\t"
        "LD_%=:\n\t}"
        :: "r"(a), "r"(parity) : "memory");
}
__device__ __forceinline__ void mma_f16(float* c, const uint32_t* a, const uint32_t* b) {
    asm volatile(
        "mma.sync.aligned.m16n8k16.row.col.f32.f16.f16.f32 "
        "{%0,%1,%2,%3}, {%4,%5,%6,%7}, {%8,%9}, {%0,%1,%2,%3};"
        : "+f"(c[0]), "+f"(c[1]), "+f"(c[2]), "+f"(c[3])
        : "r"(a[0]), "r"(a[1]), "r"(a[2]), "r"(a[3]),
          "r"(b[0]), "r"(b[1]));
}
__device__ __forceinline__ void ldsm4(uint32_t* r, uint32_t addr) {
    asm volatile("ldmatrix.sync.aligned.m8n8.x4.shared.b16 {%0,%1,%2,%3}, [%4];"
                 : "=r"(r[0]), "=r"(r[1]), "=r"(r[2]), "=r"(r[3]) : "r"(addr));
}

// ---------------- warp-specialized fp16 GEMM core ----------------
// C[m,n] = alpha * sum_k A[m,k]*B[n,k]; A [M][K] halfs, B [N][K] halfs.
// 160 threads: warps 0-3 consumers (64x64 each), warp 4 producer.
// 4-stage ring, BK=32, register-double-buffered LDSM fragments.
// Ring ordering (deadlock-free): finish reading stage s -> arrive empty[s]
// -> MMA -> wait full[s+1] -> prefetch next.
template<bool BIASROW, bool BIASCOL, bool RESID, bool SCORES, bool COLSCALE, bool OUTHALF>
__device__ __forceinline__ void gemm_core(
    const __half* __restrict__ A, const __half* __restrict__ B,
    void* __restrict__ Cv,
    const float* __restrict__ biasR, const float* __restrict__ biasC,
    const float* __restrict__ res,
    float* __restrict__ rowsum, const float* __restrict__ colsum,
    int K, int ldc, float alpha, int m0, int n0)
{
    extern __shared__ __align__(16) char smem_raw[];
    const uint32_t sb = smem_u32(smem_raw);
    __half* data = (__half*)(smem_raw + 1024);

    const int tid  = threadIdx.x;
    const int lane = tid & 31;
    const int warp = tid >> 5;

    if (tid == 0) {
        #pragma unroll
        for (int s = 0; s < NSTG; s++) {
            mbar_init(sb + s*8, 32);        // full
            mbar_init(sb + 32 + s*8, 128);  // empty
        }
    }
    __syncthreads();

    const int T = K / BK;

    if (warp == 4) {
        // ---------------- producer ----------------
        for (int t = 0; t < T; t++) {
            const int s = t & (NSTG-1);
            if (t >= NSTG) {
                mbar_wait(sb + 32 + s*8, ((t - NSTG) >> 2) & 1);
            }
            __half* Ab = data + s*(2*STG_HALFS);
            __half* Bb = Ab + STG_HALFS;
            const int k0 = t * BK;
            #pragma unroll
            for (int i = 0; i < 16; i++) {
                int idx = lane + i*32;
                int row = idx >> 2, seg = (idx & 3) * 8;
                cp16(smem_u32(Ab + row*PIT + seg), A + (size_t)(m0 + row)*K + k0 + seg);
            }
            #pragma unroll
            for (int i = 0; i < 16; i++) {
                int idx = lane + i*32;
                int row = idx >> 2, seg = (idx & 3) * 8;
                cp16(smem_u32(Bb + row*PIT + seg), B + (size_t)(n0 + row)*K + k0 + seg);
            }
            asm volatile("cp.async.commit_group;" ::: "memory");
            if (t >= 3) {
                asm volatile("cp.async.wait_group 3;" ::: "memory");
                mbar_arrive(sb + ((t - 3) & (NSTG-1))*8);
            }
        }
        asm volatile("cp.async.wait_group 2;" ::: "memory");
        mbar_arrive(sb + ((T - 3) & (NSTG-1))*8);
        asm volatile("cp.async.wait_group 1;" ::: "memory");
        mbar_arrive(sb + ((T - 2) & (NSTG-1))*8);
        asm volatile("cp.async.wait_group 0;" ::: "memory");
        mbar_arrive(sb + ((T - 1) & (NSTG-1))*8);
        return;
    }

    // ---------------- consumers ----------------
    const int wm = (warp & 1) * 64;
    const int wn = (warp >> 1) * 64;
    const int g  = lane >> 2;
    const int tg = lane & 3;

    const int a_r = (lane & 7) + ((lane >> 3) & 1) * 8;
    const int a_k = (lane >> 4) * 8;
    const int b_n = ((lane >> 4) * 8) + (lane & 7);
    const int b_k = ((lane >> 3) & 1) * 8;

    float acc[4][8][4];
    #pragma unroll
    for (int i = 0; i < 4; i++)
        #pragma unroll
        for (int j = 0; j < 8; j++)
            #pragma unroll
            for (int r = 0; r < 4; r++) acc[i][j][r] = 0.f;

    uint32_t af0[4][4], bf0[8][2];   // even k16-step fragments
    uint32_t af1[4][4], bf1[8][2];   // odd  k16-step fragments

    auto ldsm_frags = [&](uint32_t (&af)[4][4], uint32_t (&bf)[8][2],
                          const __half* Ah, const __half* Bh, int kk2) {
        #pragma unroll
        for (int mi = 0; mi < 4; mi++)
            ldsm4(af[mi], smem_u32(Ah + (wm + mi*16 + a_r)*PIT + kk2*16 + a_k));
        #pragma unroll
        for (int p = 0; p < 4; p++) {
            uint32_t r[4];
            ldsm4(r, smem_u32(Bh + (wn + p*16 + b_n)*PIT + kk2*16 + b_k));
            bf[2*p  ][0] = r[0]; bf[2*p  ][1] = r[1];
            bf[2*p+1][0] = r[2]; bf[2*p+1][1] = r[3];
        }
    };
    auto mma_all = [&](uint32_t (&af)[4][4], uint32_t (&bf)[8][2]) {
        #pragma unroll
        for (int ni = 0; ni < 8; ni++)
            #pragma unroll
            for (int mi = 0; mi < 4; mi++)
                mma_f16(acc[mi][ni], af[mi], bf[ni]);
    };

    // prologue: wait tile 0, load its kk2=0 fragments
    mbar_wait(sb + 0, 0);
    ldsm_frags(af0, bf0, data, data + STG_HALFS, 0);

    for (int t = 0; t < T; t++) {
        const int s = t & (NSTG-1);
        const __half* Ah = data + s*(2*STG_HALFS);
        const __half* Bh = Ah + STG_HALFS;

        // finish ALL reads of stage s, then release it immediately
        ldsm_frags(af1, bf1, Ah, Bh, 1);
        mbar_arrive(sb + 32 + s*8);

        // MMA kk2=0 while producer can refill stage s
        mma_all(af0, bf0);

        // prefetch kk2=0 of NEXT tile
        if (t + 1 < T) {
            const int sn = (t + 1) & (NSTG-1);
            mbar_wait(sb + sn*8, ((t + 1) >> 2) & 1);
            const __half* Ah2 = data + sn*(2*STG_HALFS);
            ldsm_frags(af0, bf0, Ah2, Ah2 + STG_HALFS, 0);
        }
        // MMA kk2=1
        mma_all(af1, bf1);
    }

    // ---- epilogue ----
    #pragma unroll
    for (int mi = 0; mi < 4; mi++) {
        int row0 = m0 + wm + mi*16 + g;
        int row1 = row0 + 8;
        float b0 = BIASROW ? biasR[row0] : 0.f;
        float b1 = BIASROW ? biasR[row1] : 0.f;
        float sum0 = 0.f, sum1 = 0.f;
        #pragma unroll
        for (int ni = 0; ni < 8; ni++) {
            int col = n0 + wn + ni*8 + 2*tg;
            float c0 = acc[mi][ni][0]*alpha;
            float c1 = acc[mi][ni][1]*alpha;
            float c2 = acc[mi][ni][2]*alpha;
            float c3 = acc[mi][ni][3]*alpha;
            if (SCORES) {
                c0 = __expf(c0); c1 = __expf(c1);
                c2 = __expf(c2); c3 = __expf(c3);
                sum0 += c0 + c1;
                sum1 += c2 + c3;
            }
            if (COLSCALE) {
                float i0 = colsum[col];       // already reciprocal
                float i1 = colsum[col + 1];
                c0 *= i0; c1 *= i1; c2 *= i0; c3 *= i1;
            }
            if (BIASCOL) {
                c0 += biasC[col]; c1 += biasC[col + 1];
                c2 += biasC[col]; c3 += biasC[col + 1];
            }
            c0 += b0; c1 += b0; c2 += b1; c3 += b1;
            if (RESID) {
                c0 += res[(size_t)row0*ldc + col];
                c1 += res[(size_t)row0*ldc + col + 1];
                c2 += res[(size_t)row1*ldc + col];
                c3 += res[(size_t)row1*ldc + col + 1];
            }
            if (OUTHALF) {
                __half* Ch = (__half*)Cv;
                *(__half2*)(Ch + (size_t)row0*ldc + col) = __floats2half2_rn(c0, c1);
                *(__half2*)(Ch + (size_t)row1*ldc + col) = __floats2half2_rn(c2, c3);
            } else {
                float* Cf = (float*)Cv;
                *(float2*)(Cf + (size_t)row0*ldc + col) = make_float2(c0, c1);
                *(float2*)(Cf + (size_t)row1*ldc + col) = make_float2(c2, c3);
            }
        }
        if (SCORES) {
            sum0 += __shfl_xor_sync(0xffffffffu, sum0, 1);
            sum0 += __shfl_xor_sync(0xffffffffu, sum0, 2);
            sum1 += __shfl_xor_sync(0xffffffffu, sum1, 1);
            sum1 += __shfl_xor_sync(0xffffffffu, sum1, 2);
            if (tg == 0) {
                atomicAdd(rowsum + row0, sum0);
                atomicAdd(rowsum + row1, sum1);
            }
        }
    }
}

// ---------------- kernel wrappers ----------------
// fused q/k/v. grid (12, 32, BATCH): x = sel*4 + nt (sel 0=q,1=k,2=v)
__global__ void __launch_bounds__(160, 2) qkv_kernel(
    const float* __restrict__ bq, const float* __restrict__ bk,
    const float* __restrict__ bv)
{
    const int b = blockIdx.z;
    const int sel = blockIdx.x >> 2;
    const int nt  = blockIdx.x & 3;
    if (sel < 2) {
        gemm_core<false, true, false, false, false, true>(
            g_hnT + (size_t)b*NPIX*CH, g_wh + (size_t)sel*CH*CH,
            (sel ? g_kT : g_qT) + (size_t)b*NPIX*CH,
            nullptr, sel ? bk : bq, nullptr, nullptr, nullptr,
            CH, CH, 1.f, blockIdx.y*128, nt*128);
    } else {
        gemm_core<true, false, false, false, false, true>(
            g_wh + (size_t)2*CH*CH, g_hnT + (size_t)b*NPIX*CH,
            g_v + (size_t)b*CH*NPIX,
            bv, nullptr, nullptr, nullptr, nullptr,
            CH, NPIX, 1.f, nt*128, blockIdx.y*128);
    }
}

__global__ void __launch_bounds__(160, 2) scores_kernel(float scale)
{
    const int b = blockIdx.z;
    gemm_core<false, false, false, true, false, true>(
        g_qT + (size_t)b*NPIX*CH, g_kT + (size_t)b*NPIX*CH,
        g_e + (size_t)b*NPIX*NPIX,
        nullptr, nullptr, nullptr, g_S + (size_t)b*NPIX, nullptr,
        CH, NPIX, scale, blockIdx.y*128, blockIdx.x*128);
}

__global__ void __launch_bounds__(160, 2) av_kernel()
{
    const int b = blockIdx.z;
    gemm_core<false, false, false, false, false, true>(
        g_e + (size_t)b*NPIX*NPIX, g_v + (size_t)b*CH*NPIX,
        g_oT + (size_t)b*NPIX*CH,
        nullptr, nullptr, nullptr, nullptr, nullptr,
        NPIX, CH, 1.f, blockIdx.y*128, blockIdx.x*128);
}

__global__ void __launch_bounds__(160, 2) outconv_kernel(
    const float* __restrict__ bo, const float* __restrict__ x,
    float* __restrict__ out)
{
    const int b = blockIdx.z;
    gemm_core<true, false, true, false, true, false>(
        g_wh + (size_t)3*CH*CH, g_oT + (size_t)b*NPIX*CH,
        out + (size_t)b*CH*NPIX,
        bo, nullptr, x + (size_t)b*CH*NPIX, nullptr, g_Sinv + (size_t)b*NPIX,
        CH, NPIX, 1.f, blockIdx.y*128, blockIdx.x*128);
}

// ---------------- launch ----------------
extern "C" void kernel_launch(void* const* d_in, const int* in_sizes, int n_in,
                              void* d_out, int out_size)
{
    const float* x     = (const float*)d_in[0];
    const float* gamma = (const float*)d_in[1];
    const float* beta  = (const float*)d_in[2];
    const float* wq    = (const float*)d_in[3];
    const float* bq    = (const float*)d_in[4];
    const float* wk    = (const float*)d_in[5];
    const float* bk    = (const float*)d_in[6];
    const float* wv    = (const float*)d_in[7];
    const float* bv    = (const float*)d_in[8];
    const float* wo    = (const float*)d_in[9];
    const float* bo    = (const float*)d_in[10];
    float* out = (float*)d_out;

    cudaFuncSetAttribute(qkv_kernel,    cudaFuncAttributeMaxDynamicSharedMemorySize, SMEM_BYTES);
    cudaFuncSetAttribute(scores_kernel, cudaFuncAttributeMaxDynamicSharedMemorySize, SMEM_BYTES);
    cudaFuncSetAttribute(av_kernel,     cudaFuncAttributeMaxDynamicSharedMemorySize, SMEM_BYTES);
    cudaFuncSetAttribute(outconv_kernel,cudaFuncAttributeMaxDynamicSharedMemorySize, SMEM_BYTES);

    const float scale = rsqrtf((float)CH);

    gn_stats_kernel<<<dim3(GROUPS, BATCH), 256>>>(x);
    prep_kernel<<<(4*CH*CH + 1023)/1024, 1024>>>(wq, wk, wv, wo);
    tnorm_kernel<<<dim3(NPIX/64, CH/64, BATCH), 256>>>(x, gamma, beta);

    qkv_kernel<<<dim3(12, NPIX/128, BATCH), 160, SMEM_BYTES>>>(bq, bk, bv);
    scores_kernel<<<dim3(NPIX/128, NPIX/128, BATCH), 160, SMEM_BYTES>>>(scale);
    recip_kernel<<<(BATCH*NPIX + 255)/256, 256>>>();
    av_kernel<<<dim3(CH/128, NPIX/128, BATCH), 160, SMEM_BYTES>>>();
    outconv_kernel<<<dim3(NPIX/128, CH/128, BATCH), 160, SMEM_BYTES>>>(bo, x, out);
}

// round 15
// speedup vs baseline: 1.8183x; 1.8183x over previous
#include <cuda_runtime.h>
#include <cuda_fp16.h>
#include <math.h>
#include <stdint.h>

#define BATCH  2
#define CH     512
#define NPIX   4096
#define GROUPS 32
#define CPG    16
#define EPS    1e-6f
#define NSTG   4         // pipeline stages
#define BK     32
#define PIT    40        // smem row pitch in halfs
#define STG_HALFS (128*PIT)          // per operand per stage
#define STG_BYTES (STG_HALFS*2*2)    // A+B per stage = 20480 B
#define SMEM_BYTES (1024 + NSTG*STG_BYTES)

// ---------------- scratch (device globals; no allocation) ----------------
__device__ __align__(256) __half g_hnT[(size_t)BATCH*NPIX*CH];  // [pix][ch]
__device__ __align__(256) __half g_qT [(size_t)BATCH*NPIX*CH];  // [pix][ch]
__device__ __align__(256) __half g_kT [(size_t)BATCH*NPIX*CH];  // [pix][ch]
__device__ __align__(256) __half g_v  [(size_t)BATCH*CH*NPIX];  // [ch][pix]
__device__ __align__(256) __half g_e  [(size_t)BATCH*NPIX*NPIX];// [i][j]
__device__ __align__(256) __half g_oT [(size_t)BATCH*NPIX*CH];  // [i][ch]
__device__ __align__(256) __half g_wh [(size_t)4*CH*CH];        // wq|wk|wv|wo
__device__ float g_S   [(size_t)BATCH*NPIX];
__device__ float g_Sinv[(size_t)BATCH*NPIX];
__device__ float g_stat[(size_t)BATCH*GROUPS*2];

// ---------------- GroupNorm stats ----------------
__global__ void gn_stats_kernel(const float* __restrict__ x)
{
    const int b = blockIdx.y, g = blockIdx.x;
    const size_t base = ((size_t)b*CH + (size_t)g*CPG) * NPIX;
    const float* xp = x + base;
    const int NE = CPG * NPIX;

    float s = 0.f, ss = 0.f;
    for (int i = threadIdx.x*4; i < NE; i += blockDim.x*4) {
        float4 v = *(const float4*)(xp + i);
        s  += v.x + v.y + v.z + v.w;
        ss += v.x*v.x + v.y*v.y + v.z*v.z + v.w*v.w;
    }
    __shared__ float sh1[256], sh2[256];
    sh1[threadIdx.x] = s; sh2[threadIdx.x] = ss;
    __syncthreads();
    for (int o = 128; o > 0; o >>= 1) {
        if (threadIdx.x < o) {
            sh1[threadIdx.x] += sh1[threadIdx.x + o];
            sh2[threadIdx.x] += sh2[threadIdx.x + o];
        }
        __syncthreads();
    }
    if (threadIdx.x == 0) {
        float mu  = sh1[0] / (float)NE;
        float var = sh2[0] / (float)NE - mu*mu;
        g_stat[(b*GROUPS + g)*2 + 0] = mu;
        g_stat[(b*GROUPS + g)*2 + 1] = rsqrtf(var + EPS);
    }
}

// ---------------- transpose + normalize -> hnT fp16 [pix][ch] ----------------
__global__ void tnorm_kernel(const float* __restrict__ x,
                             const float* __restrict__ gamma,
                             const float* __restrict__ beta)
{
    __shared__ float t[64][65];
    const int p0 = blockIdx.x*64, c0 = blockIdx.y*64, b = blockIdx.z;
    const float* xb = x + (size_t)b*CH*NPIX;
    __half* hb = g_hnT + (size_t)b*NPIX*CH;
    const int tid = threadIdx.x;

    #pragma unroll
    for (int i = 0; i < 4; i++) {
        int idx = tid + i*256;
        int ch = idx >> 4;
        int ps = (idx & 15) * 4;
        int c  = c0 + ch;
        float mu  = g_stat[(b*GROUPS + (c>>4))*2 + 0];
        float inv = g_stat[(b*GROUPS + (c>>4))*2 + 1] * gamma[c];
        float be  = beta[c] - mu*inv;
        float4 v = *(const float4*)(xb + (size_t)c*NPIX + p0 + ps);
        t[ch][ps+0] = v.x*inv + be;
        t[ch][ps+1] = v.y*inv + be;
        t[ch][ps+2] = v.z*inv + be;
        t[ch][ps+3] = v.w*inv + be;
    }
    __syncthreads();
    #pragma unroll
    for (int i = 0; i < 4; i++) {
        int idx = tid + i*256;
        int p  = idx >> 4;
        int cs = (idx & 15) * 4;
        __half2 h01 = __floats2half2_rn(t[cs+0][p], t[cs+1][p]);
        __half2 h23 = __floats2half2_rn(t[cs+2][p], t[cs+3][p]);
        uint2 w;
        w.x = *(uint32_t*)&h01;
        w.y = *(uint32_t*)&h23;
        *(uint2*)(hb + (size_t)(p0+p)*CH + c0 + cs) = w;
    }
}

// ---------------- prep: weight fp32->fp16 + zero rowsums ----------------
__global__ void prep_kernel(const float* __restrict__ wq, const float* __restrict__ wk,
                            const float* __restrict__ wv, const float* __restrict__ wo)
{
    int i = blockIdx.x * blockDim.x + threadIdx.x;
    if (i < BATCH*NPIX) g_S[i] = 0.f;
    const int per = CH*CH;
    if (i >= 4*per) return;
    int m = i / per, off = i - m*per;
    const float* s = (m == 0) ? wq : (m == 1) ? wk : (m == 2) ? wv : wo;
    g_wh[i] = __float2half(s[off]);
}

// ---------------- reciprocal of rowsums ----------------
__global__ void recip_kernel()
{
    int i = blockIdx.x * blockDim.x + threadIdx.x;
    if (i < BATCH*NPIX) g_Sinv[i] = __fdividef(1.f, g_S[i]);
}

// ---------------- low-level helpers ----------------
__device__ __forceinline__ uint32_t smem_u32(const void* p) {
    return (uint32_t)__cvta_generic_to_shared(p);
}
__device__ __forceinline__ void cp16(uint32_t dst, const __half* src) {
    asm volatile("cp.async.cg.shared.global [%0], [%1], 16;" :: "r"(dst), "l"(src));
}
__device__ __forceinline__ void mbar_init(uint32_t a, uint32_t cnt) {
    asm volatile("mbarrier.init.shared.b64 [%0], %1;" :: "r"(a), "r"(cnt) : "memory");
}
__device__ __forceinline__ void mbar_arrive(uint32_t a) {
    asm volatile("mbarrier.arrive.shared.b64 _, [%0];" :: "r"(a) : "memory");
}
__device__ __forceinline__ void mbar_wait(uint32_t a, uint32_t parity) {
    asm volatile(
        "{\n\t.reg .pred P;\n\t"
        "LW_%=:\n\t"
        "mbarrier.try_wait.parity.acquire.cta.shared::cta.b64 P, [%0], %1, 0x989680;\n\t"
        "@P bra LD_%=;\n\t"
        "bra LW_%=;\n\t"
        "LD_%=:\n\t}"
        :: "r"(a), "r"(parity) : "memory");
}
__device__ __forceinline__ void mma_f16(float* c, const uint32_t* a, const uint32_t* b) {
    asm volatile(
        "mma.sync.aligned.m16n8k16.row.col.f32.f16.f16.f32 "
        "{%0,%1,%2,%3}, {%4,%5,%6,%7}, {%8,%9}, {%0,%1,%2,%3};"
        : "+f"(c[0]), "+f"(c[1]), "+f"(c[2]), "+f"(c[3])
        : "r"(a[0]), "r"(a[1]), "r"(a[2]), "r"(a[3]),
          "r"(b[0]), "r"(b[1]));
}
__device__ __forceinline__ void ldsm4(uint32_t* r, uint32_t addr) {
    asm volatile("ldmatrix.sync.aligned.m8n8.x4.shared.b16 {%0,%1,%2,%3}, [%4];"
                 : "=r"(r[0]), "=r"(r[1]), "=r"(r[2]), "=r"(r[3]) : "r"(addr));
}

// ---------------- warp-specialized fp16 GEMM core (round-12 config) ----------------
// C[m,n] = alpha * sum_k A[m,k]*B[n,k]; A [M][K] halfs, B [N][K] halfs.
// 160 threads: warps 0-3 consumers (64x64 each), warp 4 producer.
// 4-stage mbarrier ring, BK=32, LDSM fragment loads.
template<bool BIASROW, bool BIASCOL, bool RESID, bool SCORES, bool COLSCALE, bool OUTHALF>
__device__ __forceinline__ void gemm_core(
    const __half* __restrict__ A, const __half* __restrict__ B,
    void* __restrict__ Cv,
    const float* __restrict__ biasR, const float* __restrict__ biasC,
    const float* __restrict__ res,
    float* __restrict__ rowsum, const float* __restrict__ colsum,
    int K, int ldc, float alpha, int m0, int n0)
{
    extern __shared__ __align__(16) char smem_raw[];
    const uint32_t sb = smem_u32(smem_raw);
    __half* data = (__half*)(smem_raw + 1024);

    const int tid  = threadIdx.x;
    const int lane = tid & 31;
    const int warp = tid >> 5;

    if (tid == 0) {
        #pragma unroll
        for (int s = 0; s < NSTG; s++) {
            mbar_init(sb + s*8, 32);        // full
            mbar_init(sb + 32 + s*8, 128);  // empty
        }
    }
    __syncthreads();

    const int T = K / BK;

    if (warp == 4) {
        // ---------------- producer ----------------
        for (int t = 0; t < T; t++) {
            const int s = t & (NSTG-1);
            if (t >= NSTG) {
                mbar_wait(sb + 32 + s*8, ((t - NSTG) >> 2) & 1);
            }
            __half* Ab = data + s*(2*STG_HALFS);
            __half* Bb = Ab + STG_HALFS;
            const int k0 = t * BK;
            #pragma unroll
            for (int i = 0; i < 16; i++) {
                int idx = lane + i*32;
                int row = idx >> 2, seg = (idx & 3) * 8;
                cp16(smem_u32(Ab + row*PIT + seg), A + (size_t)(m0 + row)*K + k0 + seg);
            }
            #pragma unroll
            for (int i = 0; i < 16; i++) {
                int idx = lane + i*32;
                int row = idx >> 2, seg = (idx & 3) * 8;
                cp16(smem_u32(Bb + row*PIT + seg), B + (size_t)(n0 + row)*K + k0 + seg);
            }
            asm volatile("cp.async.commit_group;" ::: "memory");
            if (t >= 3) {
                asm volatile("cp.async.wait_group 3;" ::: "memory");
                mbar_arrive(sb + ((t - 3) & (NSTG-1))*8);
            }
        }
        asm volatile("cp.async.wait_group 2;" ::: "memory");
        mbar_arrive(sb + ((T - 3) & (NSTG-1))*8);
        asm volatile("cp.async.wait_group 1;" ::: "memory");
        mbar_arrive(sb + ((T - 2) & (NSTG-1))*8);
        asm volatile("cp.async.wait_group 0;" ::: "memory");
        mbar_arrive(sb + ((T - 1) & (NSTG-1))*8);
        return;
    }

    // ---------------- consumers ----------------
    const int wm = (warp & 1) * 64;
    const int wn = (warp >> 1) * 64;
    const int g  = lane >> 2;
    const int tg = lane & 3;

    const int a_r = (lane & 7) + ((lane >> 3) & 1) * 8;
    const int a_k = (lane >> 4) * 8;
    const int b_n = ((lane >> 4) * 8) + (lane & 7);
    const int b_k = ((lane >> 3) & 1) * 8;

    float acc[4][8][4];
    #pragma unroll
    for (int i = 0; i < 4; i++)
        #pragma unroll
        for (int j = 0; j < 8; j++)
            #pragma unroll
            for (int r = 0; r < 4; r++) acc[i][j][r] = 0.f;

    for (int t = 0; t < T; t++) {
        const int s = t & (NSTG-1);
        mbar_wait(sb + s*8, (t >> 2) & 1);

        const __half* Ah = data + s*(2*STG_HALFS);
        const __half* Bh = Ah + STG_HALFS;
        #pragma unroll
        for (int kk2 = 0; kk2 < 2; kk2++) {
            uint32_t af[4][4];
            #pragma unroll
            for (int mi = 0; mi < 4; mi++)
                ldsm4(af[mi], smem_u32(Ah + (wm + mi*16 + a_r)*PIT + kk2*16 + a_k));
            uint32_t bf[8][2];
            #pragma unroll
            for (int p = 0; p < 4; p++) {
                uint32_t r[4];
                ldsm4(r, smem_u32(Bh + (wn + p*16 + b_n)*PIT + kk2*16 + b_k));
                bf[2*p  ][0] = r[0]; bf[2*p  ][1] = r[1];
                bf[2*p+1][0] = r[2]; bf[2*p+1][1] = r[3];
            }
            #pragma unroll
            for (int ni = 0; ni < 8; ni++)
                #pragma unroll
                for (int mi = 0; mi < 4; mi++)
                    mma_f16(acc[mi][ni], af[mi], bf[ni]);
        }
        mbar_arrive(sb + 32 + s*8);
    }

    // ---- epilogue ----
    #pragma unroll
    for (int mi = 0; mi < 4; mi++) {
        int row0 = m0 + wm + mi*16 + g;
        int row1 = row0 + 8;
        float b0 = BIASROW ? biasR[row0] : 0.f;
        float b1 = BIASROW ? biasR[row1] : 0.f;
        float sum0 = 0.f, sum1 = 0.f;
        #pragma unroll
        for (int ni = 0; ni < 8; ni++) {
            int col = n0 + wn + ni*8 + 2*tg;
            float c0 = acc[mi][ni][0]*alpha;
            float c1 = acc[mi][ni][1]*alpha;
            float c2 = acc[mi][ni][2]*alpha;
            float c3 = acc[mi][ni][3]*alpha;
            if (SCORES) {
                c0 = __expf(c0); c1 = __expf(c1);
                c2 = __expf(c2); c3 = __expf(c3);
                sum0 += c0 + c1;
                sum1 += c2 + c3;
            }
            if (COLSCALE) {
                float i0 = colsum[col];       // pre-inverted (g_Sinv)
                float i1 = colsum[col + 1];
                c0 *= i0; c1 *= i1; c2 *= i0; c3 *= i1;
            }
            if (BIASCOL) {
                c0 += biasC[col]; c1 += biasC[col + 1];
                c2 += biasC[col]; c3 += biasC[col + 1];
            }
            c0 += b0; c1 += b0; c2 += b1; c3 += b1;
            if (RESID) {
                c0 += res[(size_t)row0*ldc + col];
                c1 += res[(size_t)row0*ldc + col + 1];
                c2 += res[(size_t)row1*ldc + col];
                c3 += res[(size_t)row1*ldc + col + 1];
            }
            if (OUTHALF) {
                __half* Ch = (__half*)Cv;
                *(__half2*)(Ch + (size_t)row0*ldc + col) = __floats2half2_rn(c0, c1);
                *(__half2*)(Ch + (size_t)row1*ldc + col) = __floats2half2_rn(c2, c3);
            } else {
                float* Cf = (float*)Cv;
                *(float2*)(Cf + (size_t)row0*ldc + col) = make_float2(c0, c1);
                *(float2*)(Cf + (size_t)row1*ldc + col) = make_float2(c2, c3);
            }
        }
        if (SCORES) {
            sum0 += __shfl_xor_sync(0xffffffffu, sum0, 1);
            sum0 += __shfl_xor_sync(0xffffffffu, sum0, 2);
            sum1 += __shfl_xor_sync(0xffffffffu, sum1, 1);
            sum1 += __shfl_xor_sync(0xffffffffu, sum1, 2);
            if (tg == 0) {
                atomicAdd(rowsum + row0, sum0);
                atomicAdd(rowsum + row1, sum1);
            }
        }
    }
}

// ---------------- kernel wrappers ----------------
// fused q/k/v. grid (12, 32, BATCH): x = sel*4 + nt (sel 0=q,1=k,2=v)
__global__ void __launch_bounds__(160, 2) qkv_kernel(
    const float* __restrict__ bq, const float* __restrict__ bk,
    const float* __restrict__ bv)
{
    const int b = blockIdx.z;
    const int sel = blockIdx.x >> 2;
    const int nt  = blockIdx.x & 3;
    if (sel < 2) {
        gemm_core<false, true, false, false, false, true>(
            g_hnT + (size_t)b*NPIX*CH, g_wh + (size_t)sel*CH*CH,
            (sel ? g_kT : g_qT) + (size_t)b*NPIX*CH,
            nullptr, sel ? bk : bq, nullptr, nullptr, nullptr,
            CH, CH, 1.f, blockIdx.y*128, nt*128);
    } else {
        gemm_core<true, false, false, false, false, true>(
            g_wh + (size_t)2*CH*CH, g_hnT + (size_t)b*NPIX*CH,
            g_v + (size_t)b*CH*NPIX,
            bv, nullptr, nullptr, nullptr, nullptr,
            CH, NPIX, 1.f, nt*128, blockIdx.y*128);
    }
}

__global__ void __launch_bounds__(160, 2) scores_kernel(float scale)
{
    const int b = blockIdx.z;
    gemm_core<false, false, false, true, false, true>(
        g_qT + (size_t)b*NPIX*CH, g_kT + (size_t)b*NPIX*CH,
        g_e + (size_t)b*NPIX*NPIX,
        nullptr, nullptr, nullptr, g_S + (size_t)b*NPIX, nullptr,
        CH, NPIX, scale, blockIdx.y*128, blockIdx.x*128);
}

__global__ void __launch_bounds__(160, 2) av_kernel()
{
    const int b = blockIdx.z;
    gemm_core<false, false, false, false, false, true>(
        g_e + (size_t)b*NPIX*NPIX, g_v + (size_t)b*CH*NPIX,
        g_oT + (size_t)b*NPIX*CH,
        nullptr, nullptr, nullptr, nullptr, nullptr,
        NPIX, CH, 1.f, blockIdx.y*128, blockIdx.x*128);
}

__global__ void __launch_bounds__(160, 2) outconv_kernel(
    const float* __restrict__ bo, const float* __restrict__ x,
    float* __restrict__ out)
{
    const int b = blockIdx.z;
    gemm_core<true, false, true, false, true, false>(
        g_wh + (size_t)3*CH*CH, g_oT + (size_t)b*NPIX*CH,
        out + (size_t)b*CH*NPIX,
        bo, nullptr, x + (size_t)b*CH*NPIX, nullptr, g_Sinv + (size_t)b*NPIX,
        CH, NPIX, 1.f, blockIdx.y*128, blockIdx.x*128);
}

// ---------------- launch ----------------
extern "C" void kernel_launch(void* const* d_in, const int* in_sizes, int n_in,
                              void* d_out, int out_size)
{
    const float* x     = (const float*)d_in[0];
    const float* gamma = (const float*)d_in[1];
    const float* beta  = (const float*)d_in[2];
    const float* wq    = (const float*)d_in[3];
    const float* bq    = (const float*)d_in[4];
    const float* wk    = (const float*)d_in[5];
    const float* bk    = (const float*)d_in[6];
    const float* wv    = (const float*)d_in[7];
    const float* bv    = (const float*)d_in[8];
    const float* wo    = (const float*)d_in[9];
    const float* bo    = (const float*)d_in[10];
    float* out = (float*)d_out;

    cudaFuncSetAttribute(qkv_kernel,    cudaFuncAttributeMaxDynamicSharedMemorySize, SMEM_BYTES);
    cudaFuncSetAttribute(scores_kernel, cudaFuncAttributeMaxDynamicSharedMemorySize, SMEM_BYTES);
    cudaFuncSetAttribute(av_kernel,     cudaFuncAttributeMaxDynamicSharedMemorySize, SMEM_BYTES);
    cudaFuncSetAttribute(outconv_kernel,cudaFuncAttributeMaxDynamicSharedMemorySize, SMEM_BYTES);

    const float scale = rsqrtf((float)CH);

    gn_stats_kernel<<<dim3(GROUPS, BATCH), 256>>>(x);
    prep_kernel<<<(4*CH*CH + 1023)/1024, 1024>>>(wq, wk, wv, wo);
    tnorm_kernel<<<dim3(NPIX/64, CH/64, BATCH), 256>>>(x, gamma, beta);

    qkv_kernel<<<dim3(12, NPIX/128, BATCH), 160, SMEM_BYTES>>>(bq, bk, bv);
    scores_kernel<<<dim3(NPIX/128, NPIX/128, BATCH), 160, SMEM_BYTES>>>(scale);
    recip_kernel<<<(BATCH*NPIX + 255)/256, 256>>>();
    av_kernel<<<dim3(CH/128, NPIX/128, BATCH), 160, SMEM_BYTES>>>();
    outconv_kernel<<<dim3(NPIX/128, CH/128, BATCH), 160, SMEM_BYTES>>>(bo, x, out);
}

// round 16
// speedup vs baseline: 1.8584x; 1.0220x over previous
#include <cuda_runtime.h>
#include <cuda_fp16.h>
#include <math.h>
#include <stdint.h>

#define BATCH  2
#define CH     512
#define NPIX   4096
#define GROUPS 32
#define CPG    16
#define EPS    1e-6f
#define NSTG   4         // pipeline stages
#define BK     32
#define PIT    40        // smem row pitch in halfs
#define STG_HALFS (128*PIT)          // per operand per stage
#define STG_BYTES (STG_HALFS*2*2)    // A+B per stage = 20480 B
#define SMEM_BYTES (1024 + NSTG*STG_BYTES)

// ---------------- scratch (device globals; no allocation) ----------------
__device__ __align__(256) __half g_hnT[(size_t)BATCH*NPIX*CH];  // [pix][ch]
__device__ __align__(256) __half g_qT [(size_t)BATCH*NPIX*CH];  // [pix][ch]
__device__ __align__(256) __half g_kT [(size_t)BATCH*NPIX*CH];  // [pix][ch]
__device__ __align__(256) __half g_v  [(size_t)BATCH*CH*NPIX];  // [ch][pix]
__device__ __align__(256) __half g_e  [(size_t)BATCH*NPIX*NPIX];// [i][j]
__device__ __align__(256) __half g_oT [(size_t)BATCH*NPIX*CH];  // [i][ch]
__device__ __align__(256) __half g_wh [(size_t)4*CH*CH];        // wq|wk|wv|wo
__device__ float g_S   [(size_t)BATCH*NPIX];
__device__ float g_stat[(size_t)BATCH*GROUPS*2];

// ---------------- setup: GroupNorm stats + weight cvt + zero S ----------------
// blocks [0, BATCH*GROUPS): gn stats; blocks [BATCH*GROUPS, ...): prep
#define GN_BLOCKS (BATCH*GROUPS)
#define PREP_ELEMS (4*CH*CH)
#define PREP_BLOCKS ((PREP_ELEMS + 255)/256)
__global__ void setup_kernel(const float* __restrict__ x,
                             const float* __restrict__ wq, const float* __restrict__ wk,
                             const float* __restrict__ wv, const float* __restrict__ wo)
{
    if (blockIdx.x < GN_BLOCKS) {
        const int b = blockIdx.x >> 5, g = blockIdx.x & 31;
        const size_t base = ((size_t)b*CH + (size_t)g*CPG) * NPIX;
        const float* xp = x + base;
        const int NE = CPG * NPIX;

        float s = 0.f, ss = 0.f;
        for (int i = threadIdx.x*4; i < NE; i += blockDim.x*4) {
            float4 v = *(const float4*)(xp + i);
            s  += v.x + v.y + v.z + v.w;
            ss += v.x*v.x + v.y*v.y + v.z*v.z + v.w*v.w;
        }
        __shared__ float sh1[256], sh2[256];
        sh1[threadIdx.x] = s; sh2[threadIdx.x] = ss;
        __syncthreads();
        for (int o = 128; o > 0; o >>= 1) {
            if (threadIdx.x < o) {
                sh1[threadIdx.x] += sh1[threadIdx.x + o];
                sh2[threadIdx.x] += sh2[threadIdx.x + o];
            }
            __syncthreads();
        }
        if (threadIdx.x == 0) {
            float mu  = sh1[0] / (float)NE;
            float var = sh2[0] / (float)NE - mu*mu;
            g_stat[(b*GROUPS + g)*2 + 0] = mu;
            g_stat[(b*GROUPS + g)*2 + 1] = rsqrtf(var + EPS);
        }
    } else {
        int i = (blockIdx.x - GN_BLOCKS) * blockDim.x + threadIdx.x;
        if (i < BATCH*NPIX) g_S[i] = 0.f;
        if (i >= PREP_ELEMS) return;
        const int per = CH*CH;
        int m = i / per, off = i - m*per;
        const float* s = (m == 0) ? wq : (m == 1) ? wk : (m == 2) ? wv : wo;
        g_wh[i] = __float2half(s[off]);
    }
}

// ---------------- transpose + normalize -> hnT fp16 [pix][ch] ----------------
__global__ void tnorm_kernel(const float* __restrict__ x,
                             const float* __restrict__ gamma,
                             const float* __restrict__ beta)
{
    __shared__ float t[64][65];
    const int p0 = blockIdx.x*64, c0 = blockIdx.y*64, b = blockIdx.z;
    const float* xb = x + (size_t)b*CH*NPIX;
    __half* hb = g_hnT + (size_t)b*NPIX*CH;
    const int tid = threadIdx.x;

    #pragma unroll
    for (int i = 0; i < 4; i++) {
        int idx = tid + i*256;
        int ch = idx >> 4;
        int ps = (idx & 15) * 4;
        int c  = c0 + ch;
        float mu  = g_stat[(b*GROUPS + (c>>4))*2 + 0];
        float inv = g_stat[(b*GROUPS + (c>>4))*2 + 1] * gamma[c];
        float be  = beta[c] - mu*inv;
        float4 v = *(const float4*)(xb + (size_t)c*NPIX + p0 + ps);
        t[ch][ps+0] = v.x*inv + be;
        t[ch][ps+1] = v.y*inv + be;
        t[ch][ps+2] = v.z*inv + be;
        t[ch][ps+3] = v.w*inv + be;
    }
    __syncthreads();
    #pragma unroll
    for (int i = 0; i < 4; i++) {
        int idx = tid + i*256;
        int p  = idx >> 4;
        int cs = (idx & 15) * 4;
        __half2 h01 = __floats2half2_rn(t[cs+0][p], t[cs+1][p]);
        __half2 h23 = __floats2half2_rn(t[cs+2][p], t[cs+3][p]);
        uint2 w;
        w.x = *(uint32_t*)&h01;
        w.y = *(uint32_t*)&h23;
        *(uint2*)(hb + (size_t)(p0+p)*CH + c0 + cs) = w;
    }
}

// ---------------- low-level helpers ----------------
__device__ __forceinline__ uint32_t smem_u32(const void* p) {
    return (uint32_t)__cvta_generic_to_shared(p);
}
__device__ __forceinline__ void cp16(uint32_t dst, const __half* src) {
    asm volatile("cp.async.cg.shared.global [%0], [%1], 16;" :: "r"(dst), "l"(src));
}
__device__ __forceinline__ void mbar_init(uint32_t a, uint32_t cnt) {
    asm volatile("mbarrier.init.shared.b64 [%0], %1;" :: "r"(a), "r"(cnt) : "memory");
}
__device__ __forceinline__ void mbar_arrive(uint32_t a) {
    asm volatile("mbarrier.arrive.shared.b64 _, [%0];" :: "r"(a) : "memory");
}
__device__ __forceinline__ void mbar_wait(uint32_t a, uint32_t parity) {
    asm volatile(
        "{\n\t.reg .pred P;\n\t"
        "LW_%=:\n\t"
        "mbarrier.try_wait.parity.acquire.cta.shared::cta.b64 P, [%0], %1, 0x989680;\n\t"
        "@P bra LD_%=;\n\t"
        "bra LW_%=;\n\t"
        "LD_%=:\n\t}"
        :: "r"(a), "r"(parity) : "memory");
}
// NOTE: non-volatile — pure register op; ordering enforced by data deps.
// Lets ptxas interleave HMMA with LDSM and schedule across the tile body.
__device__ __forceinline__ void mma_f16(float* c, const uint32_t* a, const uint32_t* b) {
    asm("mma.sync.aligned.m16n8k16.row.col.f32.f16.f16.f32 "
        "{%0,%1,%2,%3}, {%4,%5,%6,%7}, {%8,%9}, {%0,%1,%2,%3};"
        : "+f"(c[0]), "+f"(c[1]), "+f"(c[2]), "+f"(c[3])
        : "r"(a[0]), "r"(a[1]), "r"(a[2]), "r"(a[3]),
          "r"(b[0]), "r"(b[1]));
}
__device__ __forceinline__ void ldsm4(uint32_t* r, uint32_t addr) {
    asm volatile("ldmatrix.sync.aligned.m8n8.x4.shared.b16 {%0,%1,%2,%3}, [%4];"
                 : "=r"(r[0]), "=r"(r[1]), "=r"(r[2]), "=r"(r[3]) : "r"(addr));
}

// ---------------- warp-specialized fp16 GEMM core (round-12 config) ----------------
// C[m,n] = alpha * sum_k A[m,k]*B[n,k]; A [M][K] halfs, B [N][K] halfs.
// 160 threads: warps 0-3 consumers (64x64 each), warp 4 producer.
// 4-stage mbarrier ring, BK=32, LDSM fragment loads.
template<bool BIASROW, bool BIASCOL, bool RESID, bool SCORES, bool COLSCALE, bool OUTHALF>
__device__ __forceinline__ void gemm_core(
    const __half* __restrict__ A, const __half* __restrict__ B,
    void* __restrict__ Cv,
    const float* __restrict__ biasR, const float* __restrict__ biasC,
    const float* __restrict__ res,
    float* __restrict__ rowsum, const float* __restrict__ colsum,
    int K, int ldc, float alpha, int m0, int n0)
{
    extern __shared__ __align__(16) char smem_raw[];
    const uint32_t sb = smem_u32(smem_raw);
    __half* data = (__half*)(smem_raw + 1024);

    const int tid  = threadIdx.x;
    const int lane = tid & 31;
    const int warp = tid >> 5;

    if (tid == 0) {
        #pragma unroll
        for (int s = 0; s < NSTG; s++) {
            mbar_init(sb + s*8, 32);        // full
            mbar_init(sb + 32 + s*8, 128);  // empty
        }
    }
    __syncthreads();

    const int T = K / BK;

    if (warp == 4) {
        // ---------------- producer ----------------
        for (int t = 0; t < T; t++) {
            const int s = t & (NSTG-1);
            if (t >= NSTG) {
                mbar_wait(sb + 32 + s*8, ((t - NSTG) >> 2) & 1);
            }
            __half* Ab = data + s*(2*STG_HALFS);
            __half* Bb = Ab + STG_HALFS;
            const int k0 = t * BK;
            #pragma unroll
            for (int i = 0; i < 16; i++) {
                int idx = lane + i*32;
                int row = idx >> 2, seg = (idx & 3) * 8;
                cp16(smem_u32(Ab + row*PIT + seg), A + (size_t)(m0 + row)*K + k0 + seg);
            }
            #pragma unroll
            for (int i = 0; i < 16; i++) {
                int idx = lane + i*32;
                int row = idx >> 2, seg = (idx & 3) * 8;
                cp16(smem_u32(Bb + row*PIT + seg), B + (size_t)(n0 + row)*K + k0 + seg);
            }
            asm volatile("cp.async.commit_group;" ::: "memory");
            if (t >= 3) {
                asm volatile("cp.async.wait_group 3;" ::: "memory");
                mbar_arrive(sb + ((t - 3) & (NSTG-1))*8);
            }
        }
        asm volatile("cp.async.wait_group 2;" ::: "memory");
        mbar_arrive(sb + ((T - 3) & (NSTG-1))*8);
        asm volatile("cp.async.wait_group 1;" ::: "memory");
        mbar_arrive(sb + ((T - 2) & (NSTG-1))*8);
        asm volatile("cp.async.wait_group 0;" ::: "memory");
        mbar_arrive(sb + ((T - 1) & (NSTG-1))*8);
        return;
    }

    // ---------------- consumers ----------------
    const int wm = (warp & 1) * 64;
    const int wn = (warp >> 1) * 64;
    const int g  = lane >> 2;
    const int tg = lane & 3;

    const int a_r = (lane & 7) + ((lane >> 3) & 1) * 8;
    const int a_k = (lane >> 4) * 8;
    const int b_n = ((lane >> 4) * 8) + (lane & 7);
    const int b_k = ((lane >> 3) & 1) * 8;

    float acc[4][8][4];
    #pragma unroll
    for (int i = 0; i < 4; i++)
        #pragma unroll
        for (int j = 0; j < 8; j++)
            #pragma unroll
            for (int r = 0; r < 4; r++) acc[i][j][r] = 0.f;

    for (int t = 0; t < T; t++) {
        const int s = t & (NSTG-1);
        mbar_wait(sb + s*8, (t >> 2) & 1);

        const __half* Ah = data + s*(2*STG_HALFS);
        const __half* Bh = Ah + STG_HALFS;
        #pragma unroll
        for (int kk2 = 0; kk2 < 2; kk2++) {
            uint32_t af[4][4];
            #pragma unroll
            for (int mi = 0; mi < 4; mi++)
                ldsm4(af[mi], smem_u32(Ah + (wm + mi*16 + a_r)*PIT + kk2*16 + a_k));
            uint32_t bf[8][2];
            #pragma unroll
            for (int p = 0; p < 4; p++) {
                uint32_t r[4];
                ldsm4(r, smem_u32(Bh + (wn + p*16 + b_n)*PIT + kk2*16 + b_k));
                bf[2*p  ][0] = r[0]; bf[2*p  ][1] = r[1];
                bf[2*p+1][0] = r[2]; bf[2*p+1][1] = r[3];
            }
            #pragma unroll
            for (int ni = 0; ni < 8; ni++)
                #pragma unroll
                for (int mi = 0; mi < 4; mi++)
                    mma_f16(acc[mi][ni], af[mi], bf[ni]);
        }
        mbar_arrive(sb + 32 + s*8);
    }

    // ---- epilogue ----
    #pragma unroll
    for (int mi = 0; mi < 4; mi++) {
        int row0 = m0 + wm + mi*16 + g;
        int row1 = row0 + 8;
        float b0 = BIASROW ? biasR[row0] : 0.f;
        float b1 = BIASROW ? biasR[row1] : 0.f;
        float sum0 = 0.f, sum1 = 0.f;
        #pragma unroll
        for (int ni = 0; ni < 8; ni++) {
            int col = n0 + wn + ni*8 + 2*tg;
            float c0 = acc[mi][ni][0]*alpha;
            float c1 = acc[mi][ni][1]*alpha;
            float c2 = acc[mi][ni][2]*alpha;
            float c3 = acc[mi][ni][3]*alpha;
            if (SCORES) {
                c0 = __expf(c0); c1 = __expf(c1);
                c2 = __expf(c2); c3 = __expf(c3);
                sum0 += c0 + c1;
                sum1 += c2 + c3;
            }
            if (COLSCALE) {
                float i0 = __fdividef(1.f, colsum[col]);
                float i1 = __fdividef(1.f, colsum[col + 1]);
                c0 *= i0; c1 *= i1; c2 *= i0; c3 *= i1;
            }
            if (BIASCOL) {
                c0 += biasC[col]; c1 += biasC[col + 1];
                c2 += biasC[col]; c3 += biasC[col + 1];
            }
            c0 += b0; c1 += b0; c2 += b1; c3 += b1;
            if (RESID) {
                c0 += res[(size_t)row0*ldc + col];
                c1 += res[(size_t)row0*ldc + col + 1];
                c2 += res[(size_t)row1*ldc + col];
                c3 += res[(size_t)row1*ldc + col + 1];
            }
            if (OUTHALF) {
                __half* Ch = (__half*)Cv;
                *(__half2*)(Ch + (size_t)row0*ldc + col) = __floats2half2_rn(c0, c1);
                *(__half2*)(Ch + (size_t)row1*ldc + col) = __floats2half2_rn(c2, c3);
            } else {
                float* Cf = (float*)Cv;
                *(float2*)(Cf + (size_t)row0*ldc + col) = make_float2(c0, c1);
                *(float2*)(Cf + (size_t)row1*ldc + col) = make_float2(c2, c3);
            }
        }
        if (SCORES) {
            sum0 += __shfl_xor_sync(0xffffffffu, sum0, 1);
            sum0 += __shfl_xor_sync(0xffffffffu, sum0, 2);
            sum1 += __shfl_xor_sync(0xffffffffu, sum1, 1);
            sum1 += __shfl_xor_sync(0xffffffffu, sum1, 2);
            if (tg == 0) {
                atomicAdd(rowsum + row0, sum0);
                atomicAdd(rowsum + row1, sum1);
            }
        }
    }
}

// ---------------- kernel wrappers ----------------
// fused q/k/v. grid (12, 32, BATCH): x = sel*4 + nt (sel 0=q,1=k,2=v)
__global__ void __launch_bounds__(160, 2) qkv_kernel(
    const float* __restrict__ bq, const float* __restrict__ bk,
    const float* __restrict__ bv)
{
    const int b = blockIdx.z;
    const int sel = blockIdx.x >> 2;
    const int nt  = blockIdx.x & 3;
    if (sel < 2) {
        gemm_core<false, true, false, false, false, true>(
            g_hnT + (size_t)b*NPIX*CH, g_wh + (size_t)sel*CH*CH,
            (sel ? g_kT : g_qT) + (size_t)b*NPIX*CH,
            nullptr, sel ? bk : bq, nullptr, nullptr, nullptr,
            CH, CH, 1.f, blockIdx.y*128, nt*128);
    } else {
        gemm_core<true, false, false, false, false, true>(
            g_wh + (size_t)2*CH*CH, g_hnT + (size_t)b*NPIX*CH,
            g_v + (size_t)b*CH*NPIX,
            bv, nullptr, nullptr, nullptr, nullptr,
            CH, NPIX, 1.f, nt*128, blockIdx.y*128);
    }
}

__global__ void __launch_bounds__(160, 2) scores_kernel(float scale)
{
    const int b = blockIdx.z;
    gemm_core<false, false, false, true, false, true>(
        g_qT + (size_t)b*NPIX*CH, g_kT + (size_t)b*NPIX*CH,
        g_e + (size_t)b*NPIX*NPIX,
        nullptr, nullptr, nullptr, g_S + (size_t)b*NPIX, nullptr,
        CH, NPIX, scale, blockIdx.y*128, blockIdx.x*128);
}

__global__ void __launch_bounds__(160, 2) av_kernel()
{
    const int b = blockIdx.z;
    gemm_core<false, false, false, false, false, true>(
        g_e + (size_t)b*NPIX*NPIX, g_v + (size_t)b*CH*NPIX,
        g_oT + (size_t)b*NPIX*CH,
        nullptr, nullptr, nullptr, nullptr, nullptr,
        NPIX, CH, 1.f, blockIdx.y*128, blockIdx.x*128);
}

__global__ void __launch_bounds__(160, 2) outconv_kernel(
    const float* __restrict__ bo, const float* __restrict__ x,
    float* __restrict__ out)
{
    const int b = blockIdx.z;
    gemm_core<true, false, true, false, true, false>(
        g_wh + (size_t)3*CH*CH, g_oT + (size_t)b*NPIX*CH,
        out + (size_t)b*CH*NPIX,
        bo, nullptr, x + (size_t)b*CH*NPIX, nullptr, g_S + (size_t)b*NPIX,
        CH, NPIX, 1.f, blockIdx.y*128, blockIdx.x*128);
}

// ---------------- launch ----------------
extern "C" void kernel_launch(void* const* d_in, const int* in_sizes, int n_in,
                              void* d_out, int out_size)
{
    const float* x     = (const float*)d_in[0];
    const float* gamma = (const float*)d_in[1];
    const float* beta  = (const float*)d_in[2];
    const float* wq    = (const float*)d_in[3];
    const float* bq    = (const float*)d_in[4];
    const float* wk    = (const float*)d_in[5];
    const float* bk    = (const float*)d_in[6];
    const float* wv    = (const float*)d_in[7];
    const float* bv    = (const float*)d_in[8];
    const float* wo    = (const float*)d_in[9];
    const float* bo    = (const float*)d_in[10];
    float* out = (float*)d_out;

    cudaFuncSetAttribute(qkv_kernel,    cudaFuncAttributeMaxDynamicSharedMemorySize, SMEM_BYTES);
    cudaFuncSetAttribute(scores_kernel, cudaFuncAttributeMaxDynamicSharedMemorySize, SMEM_BYTES);
    cudaFuncSetAttribute(av_kernel,     cudaFuncAttributeMaxDynamicSharedMemorySize, SMEM_BYTES);
    cudaFuncSetAttribute(outconv_kernel,cudaFuncAttributeMaxDynamicSharedMemorySize, SMEM_BYTES);

    const float scale = rsqrtf((float)CH);

    setup_kernel<<<GN_BLOCKS + PREP_BLOCKS, 256>>>(x, wq, wk, wv, wo);
    tnorm_kernel<<<dim3(NPIX/64, CH/64, BATCH), 256>>>(x, gamma, beta);

    qkv_kernel<<<dim3(12, NPIX/128, BATCH), 160, SMEM_BYTES>>>(bq, bk, bv);
    scores_kernel<<<dim3(NPIX/128, NPIX/128, BATCH), 160, SMEM_BYTES>>>(scale);
    av_kernel<<<dim3(CH/128, NPIX/128, BATCH), 160, SMEM_BYTES>>>();
    outconv_kernel<<<dim3(NPIX/128, CH/128, BATCH), 160, SMEM_BYTES>>>(bo, x, out);
}

// round 17
// speedup vs baseline: 1.8658x; 1.0040x over previous
#include <cuda_runtime.h>
#include <cuda_fp16.h>
#include <math.h>
#include <stdint.h>

#define BATCH  2
#define CH     512
#define NPIX   4096
#define GROUPS 32
#define CPG    16
#define EPS    1e-6f
#define NSTG   4         // pipeline stages
#define BK     32
#define PIT    40        // smem row pitch in halfs
#define STG_HALFS (128*PIT)          // per operand per stage
#define STG_BYTES (STG_HALFS*2*2)    // A+B per stage = 20480 B
#define SMEM_BYTES (1024 + NSTG*STG_BYTES)

// ---------------- scratch (device globals; no allocation) ----------------
__device__ __align__(256) __half g_hnT[(size_t)BATCH*NPIX*CH];  // [pix][ch]
__device__ __align__(256) __half g_qT [(size_t)BATCH*NPIX*CH];  // [pix][ch]
__device__ __align__(256) __half g_kT [(size_t)BATCH*NPIX*CH];  // [pix][ch]
__device__ __align__(256) __half g_v  [(size_t)BATCH*CH*NPIX];  // [ch][pix]
__device__ __align__(256) __half g_e  [(size_t)BATCH*NPIX*NPIX];// [i][j]
__device__ __align__(256) __half g_oT [(size_t)BATCH*NPIX*CH];  // [i][ch]
__device__ __align__(256) __half g_wh [(size_t)4*CH*CH];        // wq|wk|wv|wo
__device__ float g_S   [(size_t)BATCH*NPIX];
__device__ float g_stat[(size_t)BATCH*GROUPS*2];

// ---------------- setup: GroupNorm stats + weight cvt + zero S ----------------
#define GN_BLOCKS (BATCH*GROUPS)
#define PREP_ELEMS (4*CH*CH)
#define PREP_BLOCKS ((PREP_ELEMS + 255)/256)
__global__ void setup_kernel(const float* __restrict__ x,
                             const float* __restrict__ wq, const float* __restrict__ wk,
                             const float* __restrict__ wv, const float* __restrict__ wo)
{
    if (blockIdx.x < GN_BLOCKS) {
        const int b = blockIdx.x >> 5, g = blockIdx.x & 31;
        const size_t base = ((size_t)b*CH + (size_t)g*CPG) * NPIX;
        const float* xp = x + base;
        const int NE = CPG * NPIX;

        float s = 0.f, ss = 0.f;
        for (int i = threadIdx.x*4; i < NE; i += blockDim.x*4) {
            float4 v = *(const float4*)(xp + i);
            s  += v.x + v.y + v.z + v.w;
            ss += v.x*v.x + v.y*v.y + v.z*v.z + v.w*v.w;
        }
        __shared__ float sh1[256], sh2[256];
        sh1[threadIdx.x] = s; sh2[threadIdx.x] = ss;
        __syncthreads();
        for (int o = 128; o > 0; o >>= 1) {
            if (threadIdx.x < o) {
                sh1[threadIdx.x] += sh1[threadIdx.x + o];
                sh2[threadIdx.x] += sh2[threadIdx.x + o];
            }
            __syncthreads();
        }
        if (threadIdx.x == 0) {
            float mu  = sh1[0] / (float)NE;
            float var = sh2[0] / (float)NE - mu*mu;
            g_stat[(b*GROUPS + g)*2 + 0] = mu;
            g_stat[(b*GROUPS + g)*2 + 1] = rsqrtf(var + EPS);
        }
    } else {
        int i = (blockIdx.x - GN_BLOCKS) * blockDim.x + threadIdx.x;
        if (i < BATCH*NPIX) g_S[i] = 0.f;
        if (i >= PREP_ELEMS) return;
        const int per = CH*CH;
        int m = i / per, off = i - m*per;
        const float* s = (m == 0) ? wq : (m == 1) ? wk : (m == 2) ? wv : wo;
        g_wh[i] = __float2half(s[off]);
    }
}

// ---------------- transpose + normalize -> hnT fp16 [pix][ch] ----------------
__global__ void tnorm_kernel(const float* __restrict__ x,
                             const float* __restrict__ gamma,
                             const float* __restrict__ beta)
{
    __shared__ float t[64][65];
    const int p0 = blockIdx.x*64, c0 = blockIdx.y*64, b = blockIdx.z;
    const float* xb = x + (size_t)b*CH*NPIX;
    __half* hb = g_hnT + (size_t)b*NPIX*CH;
    const int tid = threadIdx.x;

    #pragma unroll
    for (int i = 0; i < 4; i++) {
        int idx = tid + i*256;
        int ch = idx >> 4;
        int ps = (idx & 15) * 4;
        int c  = c0 + ch;
        float mu  = g_stat[(b*GROUPS + (c>>4))*2 + 0];
        float inv = g_stat[(b*GROUPS + (c>>4))*2 + 1] * gamma[c];
        float be  = beta[c] - mu*inv;
        float4 v = *(const float4*)(xb + (size_t)c*NPIX + p0 + ps);
        t[ch][ps+0] = v.x*inv + be;
        t[ch][ps+1] = v.y*inv + be;
        t[ch][ps+2] = v.z*inv + be;
        t[ch][ps+3] = v.w*inv + be;
    }
    __syncthreads();
    #pragma unroll
    for (int i = 0; i < 4; i++) {
        int idx = tid + i*256;
        int p  = idx >> 4;
        int cs = (idx & 15) * 4;
        __half2 h01 = __floats2half2_rn(t[cs+0][p], t[cs+1][p]);
        __half2 h23 = __floats2half2_rn(t[cs+2][p], t[cs+3][p]);
        uint2 w;
        w.x = *(uint32_t*)&h01;
        w.y = *(uint32_t*)&h23;
        *(uint2*)(hb + (size_t)(p0+p)*CH + c0 + cs) = w;
    }
}

// ---------------- low-level helpers ----------------
__device__ __forceinline__ uint32_t smem_u32(const void* p) {
    return (uint32_t)__cvta_generic_to_shared(p);
}
__device__ __forceinline__ void cp16(uint32_t dst, const __half* src) {
    asm volatile("cp.async.cg.shared.global [%0], [%1], 16;" :: "r"(dst), "l"(src));
}
__device__ __forceinline__ void mbar_init(uint32_t a, uint32_t cnt) {
    asm volatile("mbarrier.init.shared.b64 [%0], %1;" :: "r"(a), "r"(cnt) : "memory");
}
__device__ __forceinline__ void mbar_arrive(uint32_t a) {
    asm volatile("mbarrier.arrive.shared.b64 _, [%0];" :: "r"(a) : "memory");
}
__device__ __forceinline__ void mbar_wait(uint32_t a, uint32_t parity) {
    asm volatile(
        "{\n\t.reg .pred P;\n\t"
        "LW_%=:\n\t"
        "mbarrier.try_wait.parity.acquire.cta.shared::cta.b64 P, [%0], %1, 0x989680;\n\t"
        "@P bra LD_%=;\n\t"
        "bra LW_%=;\n\t"
        "LD_%=:\n\t}"
        :: "r"(a), "r"(parity) : "memory");
}
// non-volatile: pure register op; ordering enforced by data deps.
__device__ __forceinline__ void mma_f16(float* c, const uint32_t* a, const uint32_t* b) {
    asm("mma.sync.aligned.m16n8k16.row.col.f32.f16.f16.f32 "
        "{%0,%1,%2,%3}, {%4,%5,%6,%7}, {%8,%9}, {%0,%1,%2,%3};"
        : "+f"(c[0]), "+f"(c[1]), "+f"(c[2]), "+f"(c[3])
        : "r"(a[0]), "r"(a[1]), "r"(a[2]), "r"(a[3]),
          "r"(b[0]), "r"(b[1]));
}
__device__ __forceinline__ void ldsm4(uint32_t* r, uint32_t addr) {
    asm volatile("ldmatrix.sync.aligned.m8n8.x4.shared.b16 {%0,%1,%2,%3}, [%4];"
                 : "=r"(r[0]), "=r"(r[1]), "=r"(r[2]), "=r"(r[3]) : "r"(addr));
}

// ---------------- warp-specialized fp16 GEMM core ----------------
// C[m,n] = alpha * sum_k A[m,k]*B[n,k]; A [M][K] halfs, B [N][K] halfs.
// 160 threads: warps 0-3 consumers (64x64 each), warp 4 producer.
// 4-stage mbarrier ring, BK=32, LDSM fragments; empty[s] released right
// after the tile's last LDSM (before the second MMA batch).
template<bool BIASROW, bool BIASCOL, bool RESID, bool SCORES, bool COLSCALE, bool OUTHALF>
__device__ __forceinline__ void gemm_core(
    const __half* __restrict__ A, const __half* __restrict__ B,
    void* __restrict__ Cv,
    const float* __restrict__ biasR, const float* __restrict__ biasC,
    const float* __restrict__ res,
    float* __restrict__ rowsum, const float* __restrict__ colsum,
    int K, int ldc, float alpha, int m0, int n0)
{
    extern __shared__ __align__(16) char smem_raw[];
    const uint32_t sb = smem_u32(smem_raw);
    __half* data = (__half*)(smem_raw + 1024);

    const int tid  = threadIdx.x;
    const int lane = tid & 31;
    const int warp = tid >> 5;

    if (tid == 0) {
        #pragma unroll
        for (int s = 0; s < NSTG; s++) {
            mbar_init(sb + s*8, 32);        // full
            mbar_init(sb + 32 + s*8, 128);  // empty
        }
    }
    __syncthreads();

    const int T = K / BK;

    if (warp == 4) {
        // ---------------- producer ----------------
        for (int t = 0; t < T; t++) {
            const int s = t & (NSTG-1);
            if (t >= NSTG) {
                mbar_wait(sb + 32 + s*8, ((t - NSTG) >> 2) & 1);
            }
            __half* Ab = data + s*(2*STG_HALFS);
            __half* Bb = Ab + STG_HALFS;
            const int k0 = t * BK;
            #pragma unroll
            for (int i = 0; i < 16; i++) {
                int idx = lane + i*32;
                int row = idx >> 2, seg = (idx & 3) * 8;
                cp16(smem_u32(Ab + row*PIT + seg), A + (size_t)(m0 + row)*K + k0 + seg);
            }
            #pragma unroll
            for (int i = 0; i < 16; i++) {
                int idx = lane + i*32;
                int row = idx >> 2, seg = (idx & 3) * 8;
                cp16(smem_u32(Bb + row*PIT + seg), B + (size_t)(n0 + row)*K + k0 + seg);
            }
            asm volatile("cp.async.commit_group;" ::: "memory");
            if (t >= 3) {
                asm volatile("cp.async.wait_group 3;" ::: "memory");
                mbar_arrive(sb + ((t - 3) & (NSTG-1))*8);
            }
        }
        asm volatile("cp.async.wait_group 2;" ::: "memory");
        mbar_arrive(sb + ((T - 3) & (NSTG-1))*8);
        asm volatile("cp.async.wait_group 1;" ::: "memory");
        mbar_arrive(sb + ((T - 2) & (NSTG-1))*8);
        asm volatile("cp.async.wait_group 0;" ::: "memory");
        mbar_arrive(sb + ((T - 1) & (NSTG-1))*8);
        return;
    }

    // ---------------- consumers ----------------
    const int wm = (warp & 1) * 64;
    const int wn = (warp >> 1) * 64;
    const int g  = lane >> 2;
    const int tg = lane & 3;

    const int a_r = (lane & 7) + ((lane >> 3) & 1) * 8;
    const int a_k = (lane >> 4) * 8;
    const int b_n = ((lane >> 4) * 8) + (lane & 7);
    const int b_k = ((lane >> 3) & 1) * 8;

    float acc[4][8][4];
    #pragma unroll
    for (int i = 0; i < 4; i++)
        #pragma unroll
        for (int j = 0; j < 8; j++)
            #pragma unroll
            for (int r = 0; r < 4; r++) acc[i][j][r] = 0.f;

    for (int t = 0; t < T; t++) {
        const int s = t & (NSTG-1);
        mbar_wait(sb + s*8, (t >> 2) & 1);

        const __half* Ah = data + s*(2*STG_HALFS);
        const __half* Bh = Ah + STG_HALFS;

        // ---- kk2 = 0: load + MMA ----
        uint32_t af[4][4];
        uint32_t bf[8][2];
        #pragma unroll
        for (int mi = 0; mi < 4; mi++)
            ldsm4(af[mi], smem_u32(Ah + (wm + mi*16 + a_r)*PIT + a_k));
        #pragma unroll
        for (int p = 0; p < 4; p++) {
            uint32_t r[4];
            ldsm4(r, smem_u32(Bh + (wn + p*16 + b_n)*PIT + b_k));
            bf[2*p  ][0] = r[0]; bf[2*p  ][1] = r[1];
            bf[2*p+1][0] = r[2]; bf[2*p+1][1] = r[3];
        }
        #pragma unroll
        for (int ni = 0; ni < 8; ni++)
            #pragma unroll
            for (int mi = 0; mi < 4; mi++)
                mma_f16(acc[mi][ni], af[mi], bf[ni]);

        // ---- kk2 = 1: load, RELEASE stage, then MMA ----
        #pragma unroll
        for (int mi = 0; mi < 4; mi++)
            ldsm4(af[mi], smem_u32(Ah + (wm + mi*16 + a_r)*PIT + 16 + a_k));
        #pragma unroll
        for (int p = 0; p < 4; p++) {
            uint32_t r[4];
            ldsm4(r, smem_u32(Bh + (wn + p*16 + b_n)*PIT + 16 + b_k));
            bf[2*p  ][0] = r[0]; bf[2*p  ][1] = r[1];
            bf[2*p+1][0] = r[2]; bf[2*p+1][1] = r[3];
        }
        mbar_arrive(sb + 32 + s*8);   // all smem reads of stage s done
        #pragma unroll
        for (int ni = 0; ni < 8; ni++)
            #pragma unroll
            for (int mi = 0; mi < 4; mi++)
                mma_f16(acc[mi][ni], af[mi], bf[ni]);
    }

    // ---- epilogue ----
    #pragma unroll
    for (int mi = 0; mi < 4; mi++) {
        int row0 = m0 + wm + mi*16 + g;
        int row1 = row0 + 8;
        float b0 = BIASROW ? biasR[row0] : 0.f;
        float b1 = BIASROW ? biasR[row1] : 0.f;
        float sum0 = 0.f, sum1 = 0.f;
        #pragma unroll
        for (int ni = 0; ni < 8; ni++) {
            int col = n0 + wn + ni*8 + 2*tg;
            float c0 = acc[mi][ni][0]*alpha;
            float c1 = acc[mi][ni][1]*alpha;
            float c2 = acc[mi][ni][2]*alpha;
            float c3 = acc[mi][ni][3]*alpha;
            if (SCORES) {
                c0 = __expf(c0); c1 = __expf(c1);
                c2 = __expf(c2); c3 = __expf(c3);
                sum0 += c0 + c1;
                sum1 += c2 + c3;
            }
            if (COLSCALE) {
                float i0 = __fdividef(1.f, colsum[col]);
                float i1 = __fdividef(1.f, colsum[col + 1]);
                c0 *= i0; c1 *= i1; c2 *= i0; c3 *= i1;
            }
            if (BIASCOL) {
                c0 += biasC[col]; c1 += biasC[col + 1];
                c2 += biasC[col]; c3 += biasC[col + 1];
            }
            c0 += b0; c1 += b0; c2 += b1; c3 += b1;
            if (RESID) {
                c0 += res[(size_t)row0*ldc + col];
                c1 += res[(size_t)row0*ldc + col + 1];
                c2 += res[(size_t)row1*ldc + col];
                c3 += res[(size_t)row1*ldc + col + 1];
            }
            if (OUTHALF) {
                __half* Ch = (__half*)Cv;
                *(__half2*)(Ch + (size_t)row0*ldc + col) = __floats2half2_rn(c0, c1);
                *(__half2*)(Ch + (size_t)row1*ldc + col) = __floats2half2_rn(c2, c3);
            } else {
                float* Cf = (float*)Cv;
                *(float2*)(Cf + (size_t)row0*ldc + col) = make_float2(c0, c1);
                *(float2*)(Cf + (size_t)row1*ldc + col) = make_float2(c2, c3);
            }
        }
        if (SCORES) {
            sum0 += __shfl_xor_sync(0xffffffffu, sum0, 1);
            sum0 += __shfl_xor_sync(0xffffffffu, sum0, 2);
            sum1 += __shfl_xor_sync(0xffffffffu, sum1, 1);
            sum1 += __shfl_xor_sync(0xffffffffu, sum1, 2);
            if (tg == 0) {
                atomicAdd(rowsum + row0, sum0);
                atomicAdd(rowsum + row1, sum1);
            }
        }
    }
}

// ---------------- kernel wrappers ----------------
// fused q/k/v. grid (12, 32, BATCH): x = sel*4 + nt (sel 0=q,1=k,2=v)
__global__ void __launch_bounds__(160, 2) qkv_kernel(
    const float* __restrict__ bq, const float* __restrict__ bk,
    const float* __restrict__ bv)
{
    const int b = blockIdx.z;
    const int sel = blockIdx.x >> 2;
    const int nt  = blockIdx.x & 3;
    if (sel < 2) {
        gemm_core<false, true, false, false, false, true>(
            g_hnT + (size_t)b*NPIX*CH, g_wh + (size_t)sel*CH*CH,
            (sel ? g_kT : g_qT) + (size_t)b*NPIX*CH,
            nullptr, sel ? bk : bq, nullptr, nullptr, nullptr,
            CH, CH, 1.f, blockIdx.y*128, nt*128);
    } else {
        gemm_core<true, false, false, false, false, true>(
            g_wh + (size_t)2*CH*CH, g_hnT + (size_t)b*NPIX*CH,
            g_v + (size_t)b*CH*NPIX,
            bv, nullptr, nullptr, nullptr, nullptr,
            CH, NPIX, 1.f, nt*128, blockIdx.y*128);
    }
}

// scores with 8-row column-major supertile rasterization for L2 reuse
__global__ void __launch_bounds__(160, 2) scores_kernel(float scale)
{
    const int b = blockIdx.z;
    const int bid = blockIdx.y * 32 + blockIdx.x;     // 0..1023
    const int band = bid >> 8;                         // /256 -> 0..3 (8 rows x 32 cols)
    const int rem  = bid & 255;
    const int col  = rem >> 3;                         // 0..31
    const int rowi = rem & 7;                          // 0..7
    const int m0 = (band*8 + rowi) * 128;
    const int n0 = col * 128;
    gemm_core<false, false, false, true, false, true>(
        g_qT + (size_t)b*NPIX*CH, g_kT + (size_t)b*NPIX*CH,
        g_e + (size_t)b*NPIX*NPIX,
        nullptr, nullptr, nullptr, g_S + (size_t)b*NPIX, nullptr,
        CH, NPIX, scale, m0, n0);
}

__global__ void __launch_bounds__(160, 2) av_kernel()
{
    const int b = blockIdx.z;
    gemm_core<false, false, false, false, false, true>(
        g_e + (size_t)b*NPIX*NPIX, g_v + (size_t)b*CH*NPIX,
        g_oT + (size_t)b*NPIX*CH,
        nullptr, nullptr, nullptr, nullptr, nullptr,
        NPIX, CH, 1.f, blockIdx.y*128, blockIdx.x*128);
}

__global__ void __launch_bounds__(160, 2) outconv_kernel(
    const float* __restrict__ bo, const float* __restrict__ x,
    float* __restrict__ out)
{
    const int b = blockIdx.z;
    gemm_core<true, false, true, false, true, false>(
        g_wh + (size_t)3*CH*CH, g_oT + (size_t)b*NPIX*CH,
        out + (size_t)b*CH*NPIX,
        bo, nullptr, x + (size_t)b*CH*NPIX, nullptr, g_S + (size_t)b*NPIX,
        CH, NPIX, 1.f, blockIdx.y*128, blockIdx.x*128);
}

// ---------------- launch ----------------
extern "C" void kernel_launch(void* const* d_in, const int* in_sizes, int n_in,
                              void* d_out, int out_size)
{
    const float* x     = (const float*)d_in[0];
    const float* gamma = (const float*)d_in[1];
    const float* beta  = (const float*)d_in[2];
    const float* wq    = (const float*)d_in[3];
    const float* bq    = (const float*)d_in[4];
    const float* wk    = (const float*)d_in[5];
    const float* bk    = (const float*)d_in[6];
    const float* wv    = (const float*)d_in[7];
    const float* bv    = (const float*)d_in[8];
    const float* wo    = (const float*)d_in[9];
    const float* bo    = (const float*)d_in[10];
    float* out = (float*)d_out;

    cudaFuncSetAttribute(qkv_kernel,    cudaFuncAttributeMaxDynamicSharedMemorySize, SMEM_BYTES);
    cudaFuncSetAttribute(scores_kernel, cudaFuncAttributeMaxDynamicSharedMemorySize, SMEM_BYTES);
    cudaFuncSetAttribute(av_kernel,     cudaFuncAttributeMaxDynamicSharedMemorySize, SMEM_BYTES);
    cudaFuncSetAttribute(outconv_kernel,cudaFuncAttributeMaxDynamicSharedMemorySize, SMEM_BYTES);

    const float scale = rsqrtf((float)CH);

    setup_kernel<<<GN_BLOCKS + PREP_BLOCKS, 256>>>(x, wq, wk, wv, wo);
    tnorm_kernel<<<dim3(NPIX/64, CH/64, BATCH), 256>>>(x, gamma, beta);

    qkv_kernel<<<dim3(12, NPIX/128, BATCH), 160, SMEM_BYTES>>>(bq, bk, bv);
    scores_kernel<<<dim3(32, 32, BATCH), 160, SMEM_BYTES>>>(scale);
    av_kernel<<<dim3(CH/128, NPIX/128, BATCH), 160, SMEM_BYTES>>>();
    outconv_kernel<<<dim3(NPIX/128, CH/128, BATCH), 160, SMEM_BYTES>>>(bo, x, out);
}